// round 3
// baseline (speedup 1.0000x reference)
#include <cuda_runtime.h>
#include <math.h>

#define BB 8
#define TT 12
#define NNODE 1024
#define EMBD 16
#define HID 64
#define JG 24832   /* 2*97*128 */
#define JU 12416   /* 2*97*64  */

// ---------------- device scratch (allocation-free rule) -----------------------
__device__ float g_Wg[(size_t)NNODE*JG];
__device__ float g_Wu[(size_t)NNODE*JU];
__device__ float g_bg[NNODE*128];
__device__ float g_bu[NNODE*64];
__device__ float g_E1[BB*TT*NNODE*EMBD];
__device__ float g_E2[BB*TT*NNODE*EMBD];
__device__ float g_tod[BB*TT*EMBD];
__device__ float g_dow[BB*TT*EMBD];
__device__ float g_state[BB*NNODE*HID];
__device__ float g_ZS[BB*NNODE*HID];
__device__ float g_R[BB*NNODE*HID];
__device__ float g_X1g[BB*NNODE*HID];
__device__ float g_X1u[BB*NNODE*HID];
__device__ float g_AX[BB*NNODE];
__device__ float g_states[BB*TT*NNODE*HID];
__device__ float g_QKV[(size_t)BB*TT*NNODE*192];

// ---------------- fast math helpers ------------------------------------------
__device__ __forceinline__ float fast_exp_small(float s) {
    // s = relu(score), expected ~1e-7 for this problem; guarded fallback.
    if (s > 0.03f) return __expf(s);
    return 1.0f + s*(1.0f + s*(0.5f + s*(1.0f/6.0f)));
}
__device__ __forceinline__ float tanh_small(float x) {
    float x2 = x*x;
    float t = x*(1.0f - x2*((1.0f/3.0f) - x2*(2.0f/15.0f)));
    if (fabsf(x) > 0.1f) t = tanhf(x);
    return t;
}
__device__ __forceinline__ float fast_sigmoid(float x) {
    return __fdividef(1.0f, 1.0f + __expf(-x));
}

// ---------------- K0: zero state, node biases, tod/dow embeddings -------------
__global__ void k_prep(const float* __restrict__ node_emb,
                       const float* __restrict__ bg_pool,
                       const float* __restrict__ bu_pool,
                       const int* __restrict__ tod_idx,
                       const int* __restrict__ dow_idx,
                       const float* __restrict__ fc_tod_W,
                       const float* __restrict__ fc_tod_b,
                       const float* __restrict__ fc_dow_W,
                       const float* __restrict__ fc_dow_b) {
    int tid = blockIdx.x*256 + threadIdx.x;
    if (tid < BB*NNODE*HID) { g_state[tid] = 0.f; return; }
    tid -= BB*NNODE*HID;
    if (tid < NNODE*128) {
        int n = tid >> 7, o = tid & 127;
        float acc = 0.f;
        #pragma unroll
        for (int d=0; d<16; d++) acc += node_emb[n*16+d]*bg_pool[d*128+o];
        g_bg[tid] = acc; return;
    }
    tid -= NNODE*128;
    if (tid < NNODE*64) {
        int n = tid >> 6, o = tid & 63;
        float acc = 0.f;
        #pragma unroll
        for (int d=0; d<16; d++) acc += node_emb[n*16+d]*bu_pool[d*64+o];
        g_bu[tid] = acc; return;
    }
    tid -= NNODE*64;
    if (tid < BB*TT*EMBD) {
        int bt = tid >> 4, dd = tid & 15;
        g_tod[tid] = fc_tod_W[tod_idx[bt]*16+dd] + fc_tod_b[dd];
        return;
    }
    tid -= BB*TT*EMBD;
    if (tid < BB*TT*EMBD) {
        int bt = tid >> 4, dd = tid & 15;
        g_dow[tid] = fc_dow_W[dow_idx[bt]*16+dd] + fc_dow_b[dd];
        return;
    }
}

// ---------------- K0b: E1/E2 = tanh(node_emb * e{1,2}[b,t]) -------------------
__global__ void k_e12(const float* __restrict__ node_emb,
                      const int* __restrict__ tod_idx,
                      const int* __restrict__ dow_idx,
                      const float* __restrict__ T1, const float* __restrict__ T2,
                      const float* __restrict__ D1, const float* __restrict__ D2) {
    int tid = blockIdx.x*256 + threadIdx.x;
    if (tid >= BB*TT*NNODE*EMBD) return;
    int dd = tid & 15;
    int n  = (tid >> 4) & 1023;
    int bt = tid >> 14;
    int td = tod_idx[bt], dw = dow_idx[bt];
    float ne = node_emb[n*16+dd];
    float e1 = T1[td*16+dd]*D1[dw*16+dd];
    float e2 = T2[td*16+dd]*D2[dw*16+dd];
    g_E1[tid] = tanh_small(ne*e1);
    g_E2[tid] = tanh_small(ne*e2);
}

// ---------------- K1: node-adaptive weights W[n] = node_emb[n] . pool ---------
__global__ void k_wnode(const float* __restrict__ node_emb,
                        const float* __restrict__ pool, int J, int which) {
    __shared__ float emb_s[32][17];
    int n0 = blockIdx.y * 32;
    for (int i = threadIdx.x; i < 512; i += 128)
        emb_s[i>>4][i&15] = node_emb[(n0 + (i>>4))*16 + (i&15)];
    __syncthreads();
    int j0 = blockIdx.x*256 + threadIdx.x*2;
    if (j0 >= J) return;
    float w0[16], w1[16];
    #pragma unroll
    for (int d=0; d<16; d++) {
        float2 w = *(const float2*)(pool + (size_t)d*J + j0);
        w0[d] = w.x; w1[d] = w.y;
    }
    float* out = which ? g_Wu : g_Wg;
    for (int nn=0; nn<32; nn++) {
        float a0=0.f, a1=0.f;
        #pragma unroll
        for (int d=0; d<16; d++) { float e = emb_s[nn][d]; a0 += e*w0[d]; a1 += e*w1[d]; }
        *(float2*)(out + (size_t)(n0+nn)*J + j0) = make_float2(a0, a1);
    }
}

// -------- K2/K4: fused scores + softmax + aggregation (flash-style) -----------
// MG=true:  V=state, also accumulates A@x -> g_AX; writes g_X1g
// MG=false: V=g_ZS  (z*state); writes g_X1u
template<bool MG>
__global__ void k_spmm(int t, const float* __restrict__ x_data) {
    __shared__ __align__(16) float E1s[16][17];
    __shared__ __align__(16) float E2s[64][17];
    __shared__ __align__(16) float Vs[64][68];
    __shared__ __align__(16) float Pts[64][18];
    __shared__ float xt_s[64];
    __shared__ float rp_s[16][8];
    __shared__ float xp_s[16][8];
    __shared__ float rs[16], xs[16];
    int b  = blockIdx.y;
    int n0 = blockIdx.x * 16;
    int tid = threadIdx.x;  // 128
    const float* E1p = g_E1 + ((size_t)(b*TT+t)*NNODE)*EMBD;
    const float* E2p = g_E2 + ((size_t)(b*TT+t)*NNODE)*EMBD;
    const float* Vsrc = MG ? g_state : g_ZS;
    for (int i=tid; i<16*16; i+=128) E1s[i>>4][i&15] = E1p[(n0+(i>>4))*16 + (i&15)];
    if (tid < 16) { rs[tid] = 0.f; xs[tid] = 0.f; }
    float acc[2][4] = {};
    int r  = tid & 15;
    int mg = tid >> 4;
    int r0 = (tid >> 4) * 2;
    int c0 = (tid & 15) * 4;
    for (int m0=0; m0<NNODE; m0+=64) {
        __syncthreads();
        for (int i=tid; i<64*16; i+=128) E2s[i>>4][i&15] = E2p[(m0+(i>>4))*16 + (i&15)];
        for (int i=tid; i<64*16; i+=128) {
            int mm = i>>4, c4 = (i&15)*4;
            *(float4*)&Vs[mm][c4] = *(const float4*)(Vsrc + ((size_t)b*NNODE + m0+mm)*HID + c4);
        }
        if (MG) { if (tid < 64) xt_s[tid] = x_data[(size_t)(b*TT+t)*NNODE + m0 + tid]; }
        __syncthreads();
        {
            float e1r[16];
            #pragma unroll
            for (int d=0; d<16; d++) e1r[d] = E1s[r][d];
            float psum = 0.f, pxs = 0.f;
            #pragma unroll
            for (int mm=0; mm<8; mm++) {
                int m = mg*8 + mm;
                float sc = 0.f;
                #pragma unroll
                for (int d=0; d<16; d++) sc += e1r[d]*E2s[m][d];
                float p = fast_exp_small(fmaxf(sc, 0.f));
                Pts[m][r] = p;
                psum += p;
                if (MG) pxs += p * xt_s[m];
            }
            rp_s[r][mg] = psum;
            if (MG) xp_s[r][mg] = pxs;
        }
        __syncthreads();
        if (tid < 16) {
            float s0 = 0.f;
            #pragma unroll
            for (int g=0; g<8; g++) s0 += rp_s[tid][g];
            rs[tid] += s0;
            if (MG) {
                float s1 = 0.f;
                #pragma unroll
                for (int g=0; g<8; g++) s1 += xp_s[tid][g];
                xs[tid] += s1;
            }
        }
        #pragma unroll 4
        for (int m=0; m<64; m++) {
            float2 p2 = *(const float2*)&Pts[m][r0];
            float4 v  = *(const float4*)&Vs[m][c0];
            acc[0][0]+=p2.x*v.x; acc[0][1]+=p2.x*v.y; acc[0][2]+=p2.x*v.z; acc[0][3]+=p2.x*v.w;
            acc[1][0]+=p2.y*v.x; acc[1][1]+=p2.y*v.y; acc[1][2]+=p2.y*v.z; acc[1][3]+=p2.y*v.w;
        }
    }
    __syncthreads();
    float inv0 = 1.0f/rs[r0], inv1 = 1.0f/rs[r0+1];
    float* Y = MG ? g_X1g : g_X1u;
    float4 y0 = make_float4(acc[0][0]*inv0, acc[0][1]*inv0, acc[0][2]*inv0, acc[0][3]*inv0);
    float4 y1 = make_float4(acc[1][0]*inv1, acc[1][1]*inv1, acc[1][2]*inv1, acc[1][3]*inv1);
    *(float4*)(Y + ((size_t)b*NNODE + n0+r0  )*HID + c0) = y0;
    *(float4*)(Y + ((size_t)b*NNODE + n0+r0+1)*HID + c0) = y1;
    if (MG && tid < 16) g_AX[b*NNODE + n0 + tid] = xs[tid]/rs[tid];
}

// ---------------- K3: gate GEMM per node: zr = sigmoid(X[8x194]@Wg[n]) --------
__global__ void k_gate(int t, const float* __restrict__ x_data) {
    __shared__ float Xs[8][194];
    __shared__ __align__(16) float red[2][8][128];
    int n = blockIdx.x;
    int tid = threadIdx.x;  // 256
    for (int i = tid; i < 8*194; i += 256) {
        int b = i / 194, q = i % 194;
        int bt = b*TT + t;
        float v;
        if (q < 97) {
            if (q == 0)       v = x_data[(size_t)bt*NNODE + n];
            else if (q < 17)  v = g_tod[bt*16 + (q-1)];
            else if (q < 33)  v = g_dow[bt*16 + (q-17)];
            else              v = g_state[(b*NNODE+n)*HID + (q-33)];
        } else {
            int q2 = q - 97;
            if (q2 == 0)      v = g_AX[b*NNODE + n];
            else if (q2 < 17) v = g_tod[bt*16 + (q2-1)];
            else if (q2 < 33) v = g_dow[bt*16 + (q2-17)];
            else              v = g_X1g[(b*NNODE+n)*HID + (q2-33)];
        }
        Xs[b][q] = v;
    }
    __syncthreads();
    int w = tid >> 5, l = tid & 31;
    int kh = w >> 2;           // 0: kk 0..96, 1: kk 97..193
    int bp = (w & 3) * 2;      // batch pair
    int o4 = l * 4;
    const float* Wn = g_Wg + (size_t)n*JG + (size_t)kh*97*128;
    const float* X0 = &Xs[bp][kh*97];
    const float* X1 = &Xs[bp+1][kh*97];
    float a0[4] = {0,0,0,0}, a1[4] = {0,0,0,0};
    #pragma unroll 4
    for (int kk = 0; kk < 97; kk++) {
        float4 wv = *(const float4*)(Wn + kk*128 + o4);
        float xa = X0[kk], xb = X1[kk];
        a0[0]+=xa*wv.x; a0[1]+=xa*wv.y; a0[2]+=xa*wv.z; a0[3]+=xa*wv.w;
        a1[0]+=xb*wv.x; a1[1]+=xb*wv.y; a1[2]+=xb*wv.z; a1[3]+=xb*wv.w;
    }
    *(float4*)&red[kh][bp  ][o4] = make_float4(a0[0],a0[1],a0[2],a0[3]);
    *(float4*)&red[kh][bp+1][o4] = make_float4(a1[0],a1[1],a1[2],a1[3]);
    __syncthreads();
    int b = tid >> 5;
    int o = (tid*4) & 127;
    #pragma unroll
    for (int j=0; j<4; j++) {
        int oo = o + j;
        float v = red[0][b][oo] + red[1][b][oo] + g_bg[n*128 + oo];
        float s = fast_sigmoid(v);
        if (oo < 64) g_ZS[(b*NNODE+n)*HID + oo] = s * g_state[(b*NNODE+n)*HID + oo];
        else         g_R [(b*NNODE+n)*HID + (oo-64)] = s;
    }
}

// ---------------- K5: candidate GEMM + state update ---------------------------
__global__ void k_cand(int t, const float* __restrict__ x_data) {
    __shared__ float Xs[8][194];
    __shared__ __align__(16) float red[2][8][64];
    int n = blockIdx.x;
    int tid = threadIdx.x;  // 256
    for (int i = tid; i < 8*194; i += 256) {
        int b = i / 194, q = i % 194;
        int bt = b*TT + t;
        float v;
        if (q < 97) {
            if (q == 0)       v = x_data[(size_t)bt*NNODE + n];
            else if (q < 17)  v = g_tod[bt*16 + (q-1)];
            else if (q < 33)  v = g_dow[bt*16 + (q-17)];
            else              v = g_ZS[(b*NNODE+n)*HID + (q-33)];
        } else {
            int q2 = q - 97;
            if (q2 == 0)      v = g_AX[b*NNODE + n];
            else if (q2 < 17) v = g_tod[bt*16 + (q2-1)];
            else if (q2 < 33) v = g_dow[bt*16 + (q2-17)];
            else              v = g_X1u[(b*NNODE+n)*HID + (q2-33)];
        }
        Xs[b][q] = v;
    }
    __syncthreads();
    int w = tid >> 5, l = tid & 31;
    int kh = w >> 2;
    int bp = (w & 3) * 2;
    int o2 = l * 2;
    const float* Wn = g_Wu + (size_t)n*JU + (size_t)kh*97*64;
    const float* X0 = &Xs[bp][kh*97];
    const float* X1 = &Xs[bp+1][kh*97];
    float a0[2] = {0,0}, a1[2] = {0,0};
    #pragma unroll 4
    for (int kk = 0; kk < 97; kk++) {
        float2 wv = *(const float2*)(Wn + kk*64 + o2);
        float xa = X0[kk], xb = X1[kk];
        a0[0]+=xa*wv.x; a0[1]+=xa*wv.y;
        a1[0]+=xb*wv.x; a1[1]+=xb*wv.y;
    }
    *(float2*)&red[kh][bp  ][o2] = make_float2(a0[0], a0[1]);
    *(float2*)&red[kh][bp+1][o2] = make_float2(a1[0], a1[1]);
    __syncthreads();
    int b = tid >> 5;
    int o = (tid*2) & 63;
    #pragma unroll
    for (int j=0; j<2; j++) {
        int oo = o + j;
        float v  = red[0][b][oo] + red[1][b][oo] + g_bu[n*64 + oo];
        float hc = tanhf(v);
        int idx = (b*NNODE+n)*HID + oo;
        float rr = g_R[idx];
        float ns = rr * g_state[idx] + (1.0f - rr) * hc;
        g_state[idx] = ns;
        g_states[((size_t)(b*TT+t)*NNODE + n)*HID + oo] = ns;
    }
}

// ---------------- K6: QKV projection ------------------------------------------
__global__ void k_qkv(const float* __restrict__ WQ, const float* __restrict__ bQ,
                      const float* __restrict__ WK, const float* __restrict__ bK,
                      const float* __restrict__ WV, const float* __restrict__ bV) {
    __shared__ __align__(16) float Ws[64][64];
    __shared__ float bs[64];
    int tid = threadIdx.x;  // 128
    int m = blockIdx.x*128 + tid;            // m = (b*N+n)*12 + t
    int tq = m % 12; int nb = m / 12; int n = nb & 1023; int b = nb >> 10;
    float s[64];
    const float* sp = g_states + ((size_t)(b*TT+tq)*NNODE + n)*HID;
    #pragma unroll
    for (int i=0; i<16; i++) *(float4*)&s[i*4] = *(const float4*)(sp + i*4);
    for (int part=0; part<3; part++) {
        const float* W  = part==0 ? WQ : (part==1 ? WK : WV);
        const float* bb = part==0 ? bQ : (part==1 ? bK : bV);
        __syncthreads();
        for (int i=tid; i<64*64; i+=128) Ws[i>>6][i&63] = W[i];
        if (tid < 64) bs[tid] = bb[tid];
        __syncthreads();
        float* outp = g_QKV + (size_t)m*192 + part*64;
        for (int cg=0; cg<16; cg++) {
            float4 acc = *(const float4*)(bs + cg*4);
            #pragma unroll
            for (int h=0; h<64; h++) {
                float4 wv = *(const float4*)&Ws[h][cg*4];
                float sv = s[h];
                acc.x += sv*wv.x; acc.y += sv*wv.y; acc.z += sv*wv.z; acc.w += sv*wv.w;
            }
            *(float4*)(outp + cg*4) = acc;
        }
    }
}

// ---------------- K7: temporal self-attention per (b,n) -----------------------
__global__ void k_attn(float* __restrict__ out) {
    __shared__ float q_s[12][65], k_s[12][65], v_s[12][65];
    __shared__ float at[12][13];
    __shared__ float inv[12];
    int bn = blockIdx.x;
    int b = bn >> 10, n = bn & 1023;
    int tid = threadIdx.x;  // 64
    const float* base = g_QKV + (size_t)bn*12*192;
    for (int i=tid; i<12*64; i+=64) {
        int tt = i >> 6, h = i & 63;
        q_s[tt][h] = base[tt*192 + h];
        k_s[tt][h] = base[tt*192 + 64 + h];
        v_s[tt][h] = base[tt*192 + 128 + h];
    }
    __syncthreads();
    for (int idx=tid; idx<144; idx+=64) {
        int tt = idx / 12, ss = idx % 12;
        float acc = 0.f;
        #pragma unroll
        for (int h=0; h<64; h++) acc += q_s[tt][h]*k_s[ss][h];
        at[tt][ss] = acc * 0.125f;   // 1/sqrt(64)
    }
    __syncthreads();
    if (tid < 12) {
        float mx = at[tid][0];
        #pragma unroll
        for (int ss=1; ss<12; ss++) mx = fmaxf(mx, at[tid][ss]);
        float sm = 0.f;
        #pragma unroll
        for (int ss=0; ss<12; ss++) { float p = __expf(at[tid][ss]-mx); at[tid][ss]=p; sm+=p; }
        inv[tid] = 1.0f/sm;
    }
    __syncthreads();
    int h = tid;
    for (int tt=0; tt<12; tt++) {
        float acc = 0.f;
        #pragma unroll
        for (int ss=0; ss<12; ss++) acc += at[tt][ss]*v_s[ss][h];
        out[((size_t)(b*TT+tt)*NNODE + n)*HID + h] = acc*inv[tt];
    }
}

// ---------------- launch ------------------------------------------------------
extern "C" void kernel_launch(void* const* d_in, const int* in_sizes, int n_in,
                              void* d_out, int out_size) {
    const float* x_data   = (const float*)d_in[0];
    const int*   tod_idx  = (const int*)d_in[1];
    const int*   dow_idx  = (const int*)d_in[2];
    const float* T1       = (const float*)d_in[3];
    const float* T2       = (const float*)d_in[4];
    const float* D1       = (const float*)d_in[5];
    const float* D2       = (const float*)d_in[6];
    const float* node_emb = (const float*)d_in[7];
    const float* fc_tod_W = (const float*)d_in[8];
    const float* fc_tod_b = (const float*)d_in[9];
    const float* fc_dow_W = (const float*)d_in[10];
    const float* fc_dow_b = (const float*)d_in[11];
    const float* Wg_pool  = (const float*)d_in[12];
    const float* bg_pool  = (const float*)d_in[13];
    const float* Wu_pool  = (const float*)d_in[14];
    const float* bu_pool  = (const float*)d_in[15];
    const float* WQ = (const float*)d_in[16];
    const float* bQ = (const float*)d_in[17];
    const float* WK = (const float*)d_in[18];
    const float* bK = (const float*)d_in[19];
    const float* WV = (const float*)d_in[20];
    const float* bV = (const float*)d_in[21];
    float* out = (float*)d_out;

    k_prep<<<2828, 256>>>(node_emb, bg_pool, bu_pool, tod_idx, dow_idx,
                          fc_tod_W, fc_tod_b, fc_dow_W, fc_dow_b);
    k_e12<<<6144, 256>>>(node_emb, tod_idx, dow_idx, T1, T2, D1, D2);
    k_wnode<<<dim3(97, 32), 128>>>(node_emb, Wg_pool, JG, 0);
    k_wnode<<<dim3(49, 32), 128>>>(node_emb, Wu_pool, JU, 1);
    for (int t = 0; t < TT; t++) {
        k_spmm<true ><<<dim3(64, 8), 128>>>(t, x_data);
        k_gate<<<1024, 256>>>(t, x_data);
        k_spmm<false><<<dim3(64, 8), 128>>>(t, x_data);
        k_cand<<<1024, 256>>>(t, x_data);
    }
    k_qkv<<<768, 128>>>(WQ, bQ, WK, bK, WV, bV);
    k_attn<<<8192, 64>>>(out);
}